// round 5
// baseline (speedup 1.0000x reference)
#include <cuda_runtime.h>
#include <cuda_bf16.h>
#include <math.h>
#include <stdint.h>

#define N_NODES 16384
#define NGLOB   4
#define NTOTAL  (N_NODES + NGLOB)
#define DIM     256
#define HEADS   8
#define DHEAD   32
#define E_LOCAL 131072
#define E_EXP   65536
#define E_RAND  (E_LOCAL + E_EXP)
#define E_CSR   (E_RAND + 5 * N_NODES)   // +self +4 globals per node

// ---------------- scratch (static device allocations only) ----------------
__device__ float g_qkv[(size_t)NTOTAL * 3 * DIM];   // [row][q|k|v (256 each)]
__device__ float g_attn[(size_t)N_NODES * DIM];
__device__ int   g_count[N_NODES];
__device__ int   g_off[N_NODES + 1];
__device__ int   g_wptr[N_NODES];
__device__ int   g_srcbuf[E_CSR];
// split bf16 operand buffers
__device__ __nv_bfloat16 g_Ahi[(size_t)NTOTAL * DIM];
__device__ __nv_bfloat16 g_Alo[(size_t)NTOTAL * DIM];
__device__ __nv_bfloat16 g_Whi[(size_t)DIM * 768];
__device__ __nv_bfloat16 g_Wlo[(size_t)DIM * 768];

// ---------------- helpers ----------------
__device__ __forceinline__ uint32_t smem_u32(const void* p) {
    return (uint32_t)__cvta_generic_to_shared(p);
}
__device__ __forceinline__ void cp_async16(uint32_t s, const void* g) {
    asm volatile("cp.async.cg.shared.global [%0], [%1], 16;" :: "r"(s), "l"(g));
}
__device__ __forceinline__ void ldsm_x4(uint32_t addr, uint32_t& r0, uint32_t& r1,
                                        uint32_t& r2, uint32_t& r3) {
    asm volatile("ldmatrix.sync.aligned.m8n8.x4.shared.b16 {%0,%1,%2,%3}, [%4];"
                 : "=r"(r0), "=r"(r1), "=r"(r2), "=r"(r3) : "r"(addr));
}
__device__ __forceinline__ void ldsm_x4_t(uint32_t addr, uint32_t& r0, uint32_t& r1,
                                          uint32_t& r2, uint32_t& r3) {
    asm volatile("ldmatrix.sync.aligned.m8n8.x4.trans.shared.b16 {%0,%1,%2,%3}, [%4];"
                 : "=r"(r0), "=r"(r1), "=r"(r2), "=r"(r3) : "r"(addr));
}
__device__ __forceinline__ void mma_bf16(float* d, const uint32_t* a, const uint32_t* b) {
    asm volatile(
        "mma.sync.aligned.m16n8k16.row.col.f32.bf16.bf16.f32 "
        "{%0,%1,%2,%3},{%4,%5,%6,%7},{%8,%9},{%0,%1,%2,%3};"
        : "+f"(d[0]), "+f"(d[1]), "+f"(d[2]), "+f"(d[3])
        : "r"(a[0]), "r"(a[1]), "r"(a[2]), "r"(a[3]), "r"(b[0]), "r"(b[1]));
}

// ---------------- CSR build ----------------
__global__ void zero_counts_kernel() {
    int t = blockIdx.x * blockDim.x + threadIdx.x;
    if (t < N_NODES) g_count[t] = 0;
}

__global__ void count_kernel(const int* __restrict__ ei, const int* __restrict__ xi) {
    int t = blockIdx.x * blockDim.x + threadIdx.x;
    if (t < E_LOCAL) atomicAdd(&g_count[ei[E_LOCAL + t]], 1);
    if (t < E_EXP)   atomicAdd(&g_count[xi[E_EXP + t]], 1);
}

// Single-pass hierarchical scan; reserves +5 slots per node (self + 4 globals).
__global__ __launch_bounds__(512) void scan_kernel() {
    const int tid  = threadIdx.x;
    const int lane = tid & 31;
    const int wid  = tid >> 5;
    const int base = tid * 32;

    int vals[32];
#pragma unroll
    for (int i = 0; i < 32; i += 4) {
        int4 t = *(const int4*)&g_count[base + i];
        vals[i] = t.x + 5; vals[i+1] = t.y + 5; vals[i+2] = t.z + 5; vals[i+3] = t.w + 5;
    }
    int sum = 0;
#pragma unroll
    for (int i = 0; i < 32; i++) { int v = vals[i]; vals[i] = sum; sum += v; }

    int inc = sum;
#pragma unroll
    for (int o = 1; o < 32; o <<= 1) {
        int n = __shfl_up_sync(0xFFFFFFFFu, inc, o);
        if (lane >= o) inc += n;
    }
    __shared__ int wsum[16];
    if (lane == 31) wsum[wid] = inc;
    __syncthreads();
    if (wid == 0) {
        int w = (lane < 16) ? wsum[lane] : 0;
#pragma unroll
        for (int o = 1; o < 16; o <<= 1) {
            int n = __shfl_up_sync(0xFFFFFFFFu, w, o);
            if (lane >= o) w += n;
        }
        if (lane < 16) wsum[lane] = w;
    }
    __syncthreads();

    int offset = (wid ? wsum[wid - 1] : 0) + inc - sum;
#pragma unroll
    for (int i = 0; i < 32; i++) {
        int o = offset + vals[i];
        g_off[base + i]  = o;
        g_wptr[base + i] = o;
    }
    if (tid == 511) g_off[N_NODES] = wsum[15];
}

__global__ void fill_kernel(const int* __restrict__ ei, const int* __restrict__ xi) {
    int t = blockIdx.x * blockDim.x + threadIdx.x;
    if (t < E_LOCAL) {
        int d = ei[E_LOCAL + t];
        int p = atomicAdd(&g_wptr[d], 1);
        g_srcbuf[p] = ei[t];
    }
    if (t < E_EXP) {
        int d = xi[E_EXP + t];
        int p = atomicAdd(&g_wptr[d], 1);
        g_srcbuf[p] = xi[t];
    }
}

// tail 5 slots of each node's segment: self + 4 global tokens
__global__ void append_kernel() {
    int t = blockIdx.x * blockDim.x + threadIdx.x;
    if (t >= N_NODES) return;
    int base = g_off[t + 1] - 5;
    g_srcbuf[base]     = t;
    g_srcbuf[base + 1] = N_NODES;
    g_srcbuf[base + 2] = N_NODES + 1;
    g_srcbuf[base + 3] = N_NODES + 2;
    g_srcbuf[base + 4] = N_NODES + 3;
}

// ---------------- split fp32 -> bf16 hi/lo ----------------
__global__ void split_kernel(const float* __restrict__ src,
                             __nv_bfloat16* __restrict__ hi,
                             __nv_bfloat16* __restrict__ lo, int n2) {
    int t = blockIdx.x * blockDim.x + threadIdx.x;
    if (t >= n2) return;
    float2 v = ((const float2*)src)[t];
    __nv_bfloat162 h;
    h.x = __float2bfloat16(v.x); h.y = __float2bfloat16(v.y);
    __nv_bfloat162 l;
    l.x = __float2bfloat16(v.x - __bfloat162float(h.x));
    l.y = __float2bfloat16(v.y - __bfloat162float(h.y));
    ((__nv_bfloat162*)hi)[t] = h;
    ((__nv_bfloat162*)lo)[t] = l;
}

// ---------------- split-bf16 tensor-core GEMM (mma.sync) ----------------
// C[M,Ncols] = A[M,256] * W[256,Ncols] + bias ; A,W pre-split into bf16 hi/lo.
// BM=128, BN=128, BK=32, double-buffered cp.async pipeline, 8 warps, 32x64 warp tiles.
#define AS_STRIDE 40
#define BS_STRIDE 136
#define AS_OFF(buf, p) ((((buf)*2 + (p)) * 128) * AS_STRIDE)
#define BS_OFF(buf, p) (20480 + (((buf)*2 + (p)) * 32) * BS_STRIDE)
#define GEMM_SMEM_ELEMS (20480 + 4 * 32 * BS_STRIDE)
#define GEMM_SMEM_BYTES (GEMM_SMEM_ELEMS * 2)

__global__ __launch_bounds__(256) void gemm_tc_kernel(
    const __nv_bfloat16* __restrict__ Ahi, const __nv_bfloat16* __restrict__ Alo,
    const __nv_bfloat16* __restrict__ Whi, const __nv_bfloat16* __restrict__ Wlo,
    const float* __restrict__ bias, float* __restrict__ C, int M, int Ncols)
{
    extern __shared__ __nv_bfloat16 sm[];
    const int tid    = threadIdx.x;
    const int lane   = tid & 31;
    const int warp   = tid >> 5;
    const int warp_m = warp & 3;
    const int warp_n = warp >> 2;
    const int row0   = blockIdx.y * 128;
    const int col0   = blockIdx.x * 128;

    float acc[2][8][4];
#pragma unroll
    for (int i = 0; i < 2; i++)
#pragma unroll
        for (int j = 0; j < 8; j++)
#pragma unroll
            for (int q = 0; q < 4; q++) acc[i][j][q] = 0.f;

    // fragment smem coordinates
    const int fa_row  = warp_m * 32 + (lane & 15);
    const int fa_koff = (lane >> 4) << 3;
    const int fb_krow = (((lane >> 3) & 1) << 3) + (lane & 7);
    const int fb_n    = warp_n * 64 + ((lane >> 4) << 3);

    // stage loader: 2 A-chunks + 2 B-chunks per thread per hi/lo part (16B each)
    auto load_stage = [&](int kt, int buf) {
        const int k0 = kt * 32;
#pragma unroll
        for (int i = 0; i < 2; i++) {
            int c  = tid * 2 + i;          // [0,512)
            int r  = c >> 2;
            int kk = (c & 3) * 8;
            int gr = row0 + r; if (gr >= M) gr = M - 1;
            size_t gidx = (size_t)gr * DIM + k0 + kk;
            cp_async16(smem_u32(&sm[AS_OFF(buf,0) + r * AS_STRIDE + kk]), Ahi + gidx);
            cp_async16(smem_u32(&sm[AS_OFF(buf,1) + r * AS_STRIDE + kk]), Alo + gidx);
        }
#pragma unroll
        for (int i = 0; i < 2; i++) {
            int c  = tid * 2 + i;          // [0,512)
            int k  = c >> 4;
            int nn = (c & 15) * 8;
            size_t gidx = (size_t)(k0 + k) * Ncols + col0 + nn;
            cp_async16(smem_u32(&sm[BS_OFF(buf,0) + k * BS_STRIDE + nn]), Whi + gidx);
            cp_async16(smem_u32(&sm[BS_OFF(buf,1) + k * BS_STRIDE + nn]), Wlo + gidx);
        }
        asm volatile("cp.async.commit_group;" ::: "memory");
    };

    load_stage(0, 0);

    for (int kt = 0; kt < 8; kt++) {
        const int buf = kt & 1;
        if (kt + 1 < 8) {
            load_stage(kt + 1, buf ^ 1);
            asm volatile("cp.async.wait_group 1;" ::: "memory");
        } else {
            asm volatile("cp.async.wait_group 0;" ::: "memory");
        }
        __syncthreads();

#pragma unroll
        for (int ks = 0; ks < 32; ks += 16) {
            uint32_t ah[2][4], al[2][4], bh[8][2], bl[8][2];
#pragma unroll
            for (int mt = 0; mt < 2; mt++) {
                ldsm_x4(smem_u32(&sm[AS_OFF(buf,0) + (fa_row + mt*16) * AS_STRIDE + ks + fa_koff]),
                        ah[mt][0], ah[mt][1], ah[mt][2], ah[mt][3]);
                ldsm_x4(smem_u32(&sm[AS_OFF(buf,1) + (fa_row + mt*16) * AS_STRIDE + ks + fa_koff]),
                        al[mt][0], al[mt][1], al[mt][2], al[mt][3]);
            }
#pragma unroll
            for (int np = 0; np < 4; np++) {
                ldsm_x4_t(smem_u32(&sm[BS_OFF(buf,0) + (ks + fb_krow) * BS_STRIDE + fb_n + np*16]),
                          bh[np*2][0], bh[np*2][1], bh[np*2+1][0], bh[np*2+1][1]);
                ldsm_x4_t(smem_u32(&sm[BS_OFF(buf,1) + (ks + fb_krow) * BS_STRIDE + fb_n + np*16]),
                          bl[np*2][0], bl[np*2][1], bl[np*2+1][0], bl[np*2+1][1]);
            }
#pragma unroll
            for (int mt = 0; mt < 2; mt++)
#pragma unroll
                for (int nt = 0; nt < 8; nt++) {
                    mma_bf16(acc[mt][nt], ah[mt], bh[nt]);
                    mma_bf16(acc[mt][nt], ah[mt], bl[nt]);
                    mma_bf16(acc[mt][nt], al[mt], bh[nt]);
                }
        }
        __syncthreads();
    }

    // epilogue
#pragma unroll
    for (int mt = 0; mt < 2; mt++) {
        int r_base = row0 + warp_m * 32 + mt * 16 + (lane >> 2);
#pragma unroll
        for (int nt = 0; nt < 8; nt++) {
            int c = col0 + warp_n * 64 + nt * 8 + (lane & 3) * 2;
            float b0 = bias[c], b1 = bias[c + 1];
            if (r_base < M) {
                float2 v = make_float2(acc[mt][nt][0] + b0, acc[mt][nt][1] + b1);
                *(float2*)&C[(size_t)r_base * Ncols + c] = v;
            }
            if (r_base + 8 < M) {
                float2 v = make_float2(acc[mt][nt][2] + b0, acc[mt][nt][3] + b1);
                *(float2*)&C[(size_t)(r_base + 8) * Ncols + c] = v;
            }
        }
    }
}

// ---------------- attention: one warp per destination node, all 8 heads ----------------
__global__ __launch_bounds__(256) void attn_kernel() {
    int gw = (blockIdx.x * blockDim.x + threadIdx.x) >> 5;
    if (gw >= N_NODES) return;
    const int lane = threadIdx.x & 31;           // lane = head*4 + quarter
    const float scale = 0.17677669529663687f;    // 32^-0.5

    const float* Qp = g_qkv + (size_t)gw * 768 + (lane << 3);
    float q[8];
    {
        float4 q0 = *(const float4*)Qp;
        float4 q1 = *(const float4*)(Qp + 4);
        q[0] = q0.x * scale; q[1] = q0.y * scale; q[2] = q0.z * scale; q[3] = q0.w * scale;
        q[4] = q1.x * scale; q[5] = q1.y * scale; q[6] = q1.z * scale; q[7] = q1.w * scale;
    }

    float m = -INFINITY, l = 0.f;
    float acc[8];
#pragma unroll
    for (int i = 0; i < 8; i++) acc[i] = 0.f;

    const int s0 = g_off[gw];
    const int e1 = g_off[gw + 1];

    int p = s0;
    if ((e1 - s0) & 1) {
        int src = g_srcbuf[p]; p++;
        const float* Kp = g_qkv + (size_t)src * 768 + 256 + (lane << 3);
        float4 k0 = *(const float4*)Kp;
        float4 k1 = *(const float4*)(Kp + 4);
        float dot = q[0]*k0.x + q[1]*k0.y + q[2]*k0.z + q[3]*k0.w
                  + q[4]*k1.x + q[5]*k1.y + q[6]*k1.z + q[7]*k1.w;
        dot += __shfl_xor_sync(0xFFFFFFFFu, dot, 1);
        dot += __shfl_xor_sync(0xFFFFFFFFu, dot, 2);
        float mnew = fmaxf(m, dot);
        float corr = __expf(m - mnew);
        float w    = __expf(dot - mnew);
        l = l * corr + w;
        const float* Vp = Kp + 256;
        float4 v0 = *(const float4*)Vp;
        float4 v1 = *(const float4*)(Vp + 4);
        acc[0] = acc[0] * corr + w * v0.x;
        acc[1] = acc[1] * corr + w * v0.y;
        acc[2] = acc[2] * corr + w * v0.z;
        acc[3] = acc[3] * corr + w * v0.w;
        acc[4] = acc[4] * corr + w * v1.x;
        acc[5] = acc[5] * corr + w * v1.y;
        acc[6] = acc[6] * corr + w * v1.z;
        acc[7] = acc[7] * corr + w * v1.w;
        m = mnew;
    }

    for (; p < e1; p += 2) {
        int src0 = g_srcbuf[p];
        int src1 = g_srcbuf[p + 1];
        const float* K0p = g_qkv + (size_t)src0 * 768 + 256 + (lane << 3);
        const float* K1p = g_qkv + (size_t)src1 * 768 + 256 + (lane << 3);
        float4 a0 = *(const float4*)K0p;
        float4 a1 = *(const float4*)(K0p + 4);
        float4 b0 = *(const float4*)K1p;
        float4 b1 = *(const float4*)(K1p + 4);
        float d0 = q[0]*a0.x + q[1]*a0.y + q[2]*a0.z + q[3]*a0.w
                 + q[4]*a1.x + q[5]*a1.y + q[6]*a1.z + q[7]*a1.w;
        float d1 = q[0]*b0.x + q[1]*b0.y + q[2]*b0.z + q[3]*b0.w
                 + q[4]*b1.x + q[5]*b1.y + q[6]*b1.z + q[7]*b1.w;
        d0 += __shfl_xor_sync(0xFFFFFFFFu, d0, 1);
        d0 += __shfl_xor_sync(0xFFFFFFFFu, d0, 2);
        d1 += __shfl_xor_sync(0xFFFFFFFFu, d1, 1);
        d1 += __shfl_xor_sync(0xFFFFFFFFu, d1, 2);

        const float* V0p = K0p + 256;
        const float* V1p = K1p + 256;
        float4 v00 = *(const float4*)V0p;
        float4 v01 = *(const float4*)(V0p + 4);
        float4 v10 = *(const float4*)V1p;
        float4 v11 = *(const float4*)(V1p + 4);

        // update 0
        float mnew = fmaxf(m, d0);
        float corr = __expf(m - mnew);
        float w    = __expf(d0 - mnew);
        l = l * corr + w;
        acc[0] = acc[0] * corr + w * v00.x;
        acc[1] = acc[1] * corr + w * v00.y;
        acc[2] = acc[2] * corr + w * v00.z;
        acc[3] = acc[3] * corr + w * v00.w;
        acc[4] = acc[4] * corr + w * v01.x;
        acc[5] = acc[5] * corr + w * v01.y;
        acc[6] = acc[6] * corr + w * v01.z;
        acc[7] = acc[7] * corr + w * v01.w;
        m = mnew;
        // update 1
        mnew = fmaxf(m, d1);
        corr = __expf(m - mnew);
        w    = __expf(d1 - mnew);
        l = l * corr + w;
        acc[0] = acc[0] * corr + w * v10.x;
        acc[1] = acc[1] * corr + w * v10.y;
        acc[2] = acc[2] * corr + w * v10.z;
        acc[3] = acc[3] * corr + w * v10.w;
        acc[4] = acc[4] * corr + w * v11.x;
        acc[5] = acc[5] * corr + w * v11.y;
        acc[6] = acc[6] * corr + w * v11.z;
        acc[7] = acc[7] * corr + w * v11.w;
        m = mnew;
    }

    float inv = 1.f / l;
    float* outp = g_attn + (size_t)gw * 256 + (lane << 3);
#pragma unroll
    for (int i = 0; i < 8; i++) outp[i] = acc[i] * inv;
}

// ---------------- launch ----------------
extern "C" void kernel_launch(void* const* d_in, const int* in_sizes, int n_in,
                              void* d_out, int out_size) {
    const float* x      = (const float*)d_in[0];
    const int*   ei     = (const int*)d_in[1];
    const int*   xi     = (const int*)d_in[2];
    const float* W_qkv  = (const float*)d_in[3];
    const float* b_qkv  = (const float*)d_in[4];
    const float* W_out  = (const float*)d_in[5];
    const float* b_out  = (const float*)d_in[6];
    const float* gtok   = (const float*)d_in[7];
    float* out = (float*)d_out;

    float*         qkv_ptr;  cudaGetSymbolAddress((void**)&qkv_ptr, g_qkv);
    float*         attn_ptr; cudaGetSymbolAddress((void**)&attn_ptr, g_attn);
    __nv_bfloat16 *Ahi, *Alo, *Whi, *Wlo;
    cudaGetSymbolAddress((void**)&Ahi, g_Ahi);
    cudaGetSymbolAddress((void**)&Alo, g_Alo);
    cudaGetSymbolAddress((void**)&Whi, g_Whi);
    cudaGetSymbolAddress((void**)&Wlo, g_Wlo);

    static int smem_set = 0;
    if (!smem_set) {
        cudaFuncSetAttribute(gemm_tc_kernel,
                             cudaFuncAttributeMaxDynamicSharedMemorySize, GEMM_SMEM_BYTES);
        smem_set = 1;
    }

    // CSR build (+5 reserved slots per node)
    zero_counts_kernel<<<N_NODES / 256, 256>>>();
    count_kernel<<<(E_LOCAL + 255) / 256, 256>>>(ei, xi);
    scan_kernel<<<1, 512>>>();
    fill_kernel<<<(E_LOCAL + 255) / 256, 256>>>(ei, xi);
    append_kernel<<<N_NODES / 256, 256>>>();

    // split x, gtok, W_qkv
    split_kernel<<<(N_NODES * DIM / 2 + 255) / 256, 256>>>(x, Ahi, Alo, N_NODES * DIM / 2);
    split_kernel<<<2, 256>>>(gtok, Ahi + (size_t)N_NODES * DIM, Alo + (size_t)N_NODES * DIM,
                             NGLOB * DIM / 2);
    split_kernel<<<(DIM * 768 / 2 + 255) / 256, 256>>>(W_qkv, Whi, Wlo, DIM * 768 / 2);

    // QKV projection: [16388, 256] x [256, 768] + b
    {
        dim3 grid(768 / 128, (NTOTAL + 127) / 128);
        gemm_tc_kernel<<<grid, 256, GEMM_SMEM_BYTES>>>(Ahi, Alo, Whi, Wlo,
                                                       b_qkv, qkv_ptr, NTOTAL, 768);
    }

    // attention: one warp per node
    attn_kernel<<<(N_NODES * 32) / 256, 256>>>();

    // split attn result + W_out
    split_kernel<<<(N_NODES * DIM / 2 + 255) / 256, 256>>>(attn_ptr, Ahi, Alo, N_NODES * DIM / 2);
    split_kernel<<<(DIM * DIM / 2 + 255) / 256, 256>>>(W_out, Whi, Wlo, DIM * DIM / 2);

    // out projection: [16384, 256] x [256, 256] + b
    {
        dim3 grid(256 / 128, N_NODES / 128);
        gemm_tc_kernel<<<grid, 256, GEMM_SMEM_BYTES>>>(Ahi, Alo, Whi, Wlo,
                                                       b_out, out, N_NODES, 256);
    }
}

// round 6
// speedup vs baseline: 1.4363x; 1.4363x over previous
#include <cuda_runtime.h>
#include <cuda_bf16.h>
#include <cuda_fp16.h>
#include <math.h>
#include <stdint.h>

#define N_NODES 16384
#define NGLOB   4
#define NTOTAL  (N_NODES + NGLOB)
#define DIM     256
#define HEADS   8
#define DHEAD   32
#define E_LOCAL 131072
#define E_EXP   65536
#define E_CSR   (E_LOCAL + E_EXP)

// ---------------- scratch (static device allocations only) ----------------
__device__ float  g_qkv[(size_t)NTOTAL * 3 * DIM];   // [row][q|k|v (256 each)] fp32
__device__ __half g_kvh[(size_t)NTOTAL * 2 * DIM];   // [row][k 256 | v 256] fp16
__device__ float  g_attn[(size_t)N_NODES * DIM];
__device__ int    g_count[N_NODES];
__device__ int    g_off[N_NODES + 1];
__device__ int    g_wptr[N_NODES];
__device__ int    g_srcbuf[E_CSR];

// ---------------- CSR build ----------------
__global__ void zero_counts_kernel() {
    int t = blockIdx.x * blockDim.x + threadIdx.x;
    if (t < N_NODES) g_count[t] = 0;
}

__global__ void count_kernel(const int* __restrict__ ei, const int* __restrict__ xi) {
    int t = blockIdx.x * blockDim.x + threadIdx.x;
    if (t < E_LOCAL) atomicAdd(&g_count[ei[E_LOCAL + t]], 1);
    if (t < E_EXP)   atomicAdd(&g_count[xi[E_EXP + t]], 1);
}

__global__ __launch_bounds__(512) void scan_kernel() {
    const int tid  = threadIdx.x;
    const int lane = tid & 31;
    const int wid  = tid >> 5;
    const int base = tid * 32;

    int vals[32];
#pragma unroll
    for (int i = 0; i < 32; i += 4) {
        int4 t = *(const int4*)&g_count[base + i];
        vals[i] = t.x; vals[i+1] = t.y; vals[i+2] = t.z; vals[i+3] = t.w;
    }
    int sum = 0;
#pragma unroll
    for (int i = 0; i < 32; i++) { int v = vals[i]; vals[i] = sum; sum += v; }

    int inc = sum;
#pragma unroll
    for (int o = 1; o < 32; o <<= 1) {
        int n = __shfl_up_sync(0xFFFFFFFFu, inc, o);
        if (lane >= o) inc += n;
    }
    __shared__ int wsum[16];
    if (lane == 31) wsum[wid] = inc;
    __syncthreads();
    if (wid == 0) {
        int w = (lane < 16) ? wsum[lane] : 0;
#pragma unroll
        for (int o = 1; o < 16; o <<= 1) {
            int n = __shfl_up_sync(0xFFFFFFFFu, w, o);
            if (lane >= o) w += n;
        }
        if (lane < 16) wsum[lane] = w;
    }
    __syncthreads();

    int offset = (wid ? wsum[wid - 1] : 0) + inc - sum;
#pragma unroll
    for (int i = 0; i < 32; i++) {
        int o = offset + vals[i];
        g_off[base + i]  = o;
        g_wptr[base + i] = o;
    }
    if (tid == 511) g_off[N_NODES] = wsum[15];
}

__global__ void fill_kernel(const int* __restrict__ ei, const int* __restrict__ xi) {
    int t = blockIdx.x * blockDim.x + threadIdx.x;
    if (t < E_LOCAL) {
        int d = ei[E_LOCAL + t];
        int p = atomicAdd(&g_wptr[d], 1);
        g_srcbuf[p] = ei[t];
    }
    if (t < E_EXP) {
        int d = xi[E_EXP + t];
        int p = atomicAdd(&g_wptr[d], 1);
        g_srcbuf[p] = xi[t];
    }
}

// ---------------- split-bf16 tensor-core GEMM (R3-proven) ----------------
__device__ __forceinline__ uint32_t smem_u32(const void* p) {
    return (uint32_t)__cvta_generic_to_shared(p);
}
__device__ __forceinline__ void ldsm_x4(uint32_t addr, uint32_t& r0, uint32_t& r1,
                                        uint32_t& r2, uint32_t& r3) {
    asm volatile("ldmatrix.sync.aligned.m8n8.x4.shared.b16 {%0,%1,%2,%3}, [%4];"
                 : "=r"(r0), "=r"(r1), "=r"(r2), "=r"(r3) : "r"(addr));
}
__device__ __forceinline__ void ldsm_x4_t(uint32_t addr, uint32_t& r0, uint32_t& r1,
                                          uint32_t& r2, uint32_t& r3) {
    asm volatile("ldmatrix.sync.aligned.m8n8.x4.trans.shared.b16 {%0,%1,%2,%3}, [%4];"
                 : "=r"(r0), "=r"(r1), "=r"(r2), "=r"(r3) : "r"(addr));
}
__device__ __forceinline__ void mma_bf16(float* d, const uint32_t* a, const uint32_t* b) {
    asm volatile(
        "mma.sync.aligned.m16n8k16.row.col.f32.bf16.bf16.f32 "
        "{%0,%1,%2,%3},{%4,%5,%6,%7},{%8,%9},{%0,%1,%2,%3};"
        : "+f"(d[0]), "+f"(d[1]), "+f"(d[2]), "+f"(d[3])
        : "r"(a[0]), "r"(a[1]), "r"(a[2]), "r"(a[3]), "r"(b[0]), "r"(b[1]));
}

#define APAD 40
#define BPAD 136

// C[M,Ncols] = rowsel(A,Aext)[M,256] * W[256,Ncols] + bias.
// If kvh != nullptr, also writes fp16 copies of output cols [256,768) into
// kvh[row][col-256] (the K|V halves buffer).
__global__ __launch_bounds__(256) void gemm_bias_tc_kernel(
    const float* __restrict__ A, const float* __restrict__ Aext, int Msplit,
    int M, int Ncols,
    const float* __restrict__ W, const float* __restrict__ bias,
    float* __restrict__ C, __half* __restrict__ kvh)
{
    __shared__ __nv_bfloat16 As[2][128][APAD];   // [hi/lo][m][k]
    __shared__ __nv_bfloat16 Bs[2][32][BPAD];    // [hi/lo][k][n]

    const int tid    = threadIdx.x;
    const int lane   = tid & 31;
    const int warp   = tid >> 5;
    const int warp_m = warp & 3;
    const int warp_n = warp >> 2;
    const int row0   = blockIdx.y * 128;
    const int col0   = blockIdx.x * 128;

    float acc[2][8][4];
#pragma unroll
    for (int i = 0; i < 2; i++)
#pragma unroll
        for (int j = 0; j < 8; j++)
#pragma unroll
            for (int q = 0; q < 4; q++) acc[i][j][q] = 0.f;

    const int a_row = tid >> 1;
    const int a_q   = tid & 1;
    const int gr    = row0 + a_row;
    const bool a_ok = (gr < M);
    const float* a_src = a_ok ? ((gr < Msplit) ? (A + (size_t)gr * DIM)
                                               : (Aext + (size_t)(gr - Msplit) * DIM))
                              : A;

    const int b_k  = tid >> 3;
    const int b_n0 = (tid & 7) * 16;

    const int fa_row  = warp_m * 32 + (lane & 15);
    const int fa_koff = (lane >> 4) << 3;
    const int fb_krow = (((lane >> 3) & 1) << 3) + (lane & 7);
    const int fb_n    = warp_n * 64 + ((lane >> 4) << 3);

    for (int k0 = 0; k0 < DIM; k0 += 32) {
#pragma unroll
        for (int i = 0; i < 4; i++) {
            int kk = (a_q * 4 + i) * 4;
            float4 v = make_float4(0.f, 0.f, 0.f, 0.f);
            if (a_ok) v = *(const float4*)(a_src + k0 + kk);
            __nv_bfloat16 h0 = __float2bfloat16(v.x), h1 = __float2bfloat16(v.y);
            __nv_bfloat16 h2 = __float2bfloat16(v.z), h3 = __float2bfloat16(v.w);
            __nv_bfloat16 l0 = __float2bfloat16(v.x - __bfloat162float(h0));
            __nv_bfloat16 l1 = __float2bfloat16(v.y - __bfloat162float(h1));
            __nv_bfloat16 l2 = __float2bfloat16(v.z - __bfloat162float(h2));
            __nv_bfloat16 l3 = __float2bfloat16(v.w - __bfloat162float(h3));
            *(__nv_bfloat162*)&As[0][a_row][kk]     = __nv_bfloat162(h0, h1);
            *(__nv_bfloat162*)&As[0][a_row][kk + 2] = __nv_bfloat162(h2, h3);
            *(__nv_bfloat162*)&As[1][a_row][kk]     = __nv_bfloat162(l0, l1);
            *(__nv_bfloat162*)&As[1][a_row][kk + 2] = __nv_bfloat162(l2, l3);
        }
        {
            const float* wrow = W + (size_t)(k0 + b_k) * Ncols + col0 + b_n0;
#pragma unroll
            for (int i = 0; i < 4; i++) {
                float4 v = *(const float4*)(wrow + i * 4);
                int nn = b_n0 + i * 4;
                __nv_bfloat16 h0 = __float2bfloat16(v.x), h1 = __float2bfloat16(v.y);
                __nv_bfloat16 h2 = __float2bfloat16(v.z), h3 = __float2bfloat16(v.w);
                __nv_bfloat16 l0 = __float2bfloat16(v.x - __bfloat162float(h0));
                __nv_bfloat16 l1 = __float2bfloat16(v.y - __bfloat162float(h1));
                __nv_bfloat16 l2 = __float2bfloat16(v.z - __bfloat162float(h2));
                __nv_bfloat16 l3 = __float2bfloat16(v.w - __bfloat162float(h3));
                *(__nv_bfloat162*)&Bs[0][b_k][nn]     = __nv_bfloat162(h0, h1);
                *(__nv_bfloat162*)&Bs[0][b_k][nn + 2] = __nv_bfloat162(h2, h3);
                *(__nv_bfloat162*)&Bs[1][b_k][nn]     = __nv_bfloat162(l0, l1);
                *(__nv_bfloat162*)&Bs[1][b_k][nn + 2] = __nv_bfloat162(l2, l3);
            }
        }
        __syncthreads();

#pragma unroll
        for (int ks = 0; ks < 32; ks += 16) {
            uint32_t ah[2][4], al[2][4], bh[8][2], bl[8][2];
#pragma unroll
            for (int mt = 0; mt < 2; mt++) {
                ldsm_x4(smem_u32(&As[0][fa_row + mt * 16][ks + fa_koff]),
                        ah[mt][0], ah[mt][1], ah[mt][2], ah[mt][3]);
                ldsm_x4(smem_u32(&As[1][fa_row + mt * 16][ks + fa_koff]),
                        al[mt][0], al[mt][1], al[mt][2], al[mt][3]);
            }
#pragma unroll
            for (int np = 0; np < 4; np++) {
                ldsm_x4_t(smem_u32(&Bs[0][ks + fb_krow][fb_n + np * 16]),
                          bh[np*2][0], bh[np*2][1], bh[np*2+1][0], bh[np*2+1][1]);
                ldsm_x4_t(smem_u32(&Bs[1][ks + fb_krow][fb_n + np * 16]),
                          bl[np*2][0], bl[np*2][1], bl[np*2+1][0], bl[np*2+1][1]);
            }
#pragma unroll
            for (int mt = 0; mt < 2; mt++)
#pragma unroll
                for (int nt = 0; nt < 8; nt++) {
                    mma_bf16(acc[mt][nt], ah[mt], bh[nt]);
                    mma_bf16(acc[mt][nt], ah[mt], bl[nt]);
                    mma_bf16(acc[mt][nt], al[mt], bh[nt]);
                }
        }
        __syncthreads();
    }

    // epilogue (+ optional fp16 K/V mirror for cols >= 256)
#pragma unroll
    for (int mt = 0; mt < 2; mt++) {
        int r_base = row0 + warp_m * 32 + mt * 16 + (lane >> 2);
#pragma unroll
        for (int nt = 0; nt < 8; nt++) {
            int c = col0 + warp_n * 64 + nt * 8 + (lane & 3) * 2;
            float b0 = bias[c], b1 = bias[c + 1];
            if (r_base < M) {
                float2 v = make_float2(acc[mt][nt][0] + b0, acc[mt][nt][1] + b1);
                *(float2*)&C[(size_t)r_base * Ncols + c] = v;
                if (kvh && c >= 256)
                    *(__half2*)&kvh[(size_t)r_base * 512 + (c - 256)] = __float22half2_rn(v);
            }
            if (r_base + 8 < M) {
                float2 v = make_float2(acc[mt][nt][2] + b0, acc[mt][nt][3] + b1);
                *(float2*)&C[(size_t)(r_base + 8) * Ncols + c] = v;
                if (kvh && c >= 256)
                    *(__half2*)&kvh[(size_t)(r_base + 8) * 512 + (c - 256)] = __float22half2_rn(v);
            }
        }
    }
}

// ---------------- attention: one warp per destination node, fp16 K/V ----------------
__global__ __launch_bounds__(256) void attn_kernel() {
    int gw = (blockIdx.x * blockDim.x + threadIdx.x) >> 5;
    if (gw >= N_NODES) return;
    const int lane = threadIdx.x & 31;           // lane = head*4 + quarter
    const float scale = 0.17677669529663687f;    // 32^-0.5

    const float* Qp = g_qkv + (size_t)gw * 768 + (lane << 3);
    float q[8];
    {
        float4 q0 = *(const float4*)Qp;
        float4 q1 = *(const float4*)(Qp + 4);
        q[0] = q0.x * scale; q[1] = q0.y * scale; q[2] = q0.z * scale; q[3] = q0.w * scale;
        q[4] = q1.x * scale; q[5] = q1.y * scale; q[6] = q1.z * scale; q[7] = q1.w * scale;
    }

    float m = -INFINITY, l = 0.f;
    float acc[8];
#pragma unroll
    for (int i = 0; i < 8; i++) acc[i] = 0.f;

    const int s0   = g_off[gw];
    const int nloc = g_off[gw + 1] - s0;
    const int ntot = nloc + 1 + NGLOB;

    for (int it = 0; it < ntot; it++) {
        int src;
        if (it < nloc)          src = g_srcbuf[s0 + it];
        else if (it == nloc)    src = gw;
        else                    src = N_NODES + (it - nloc - 1);

        const __half* Kp = g_kvh + (size_t)src * 512 + (lane << 3);
        uint4 kraw = *(const uint4*)Kp;
        __half2 kh0 = *(__half2*)&kraw.x, kh1 = *(__half2*)&kraw.y;
        __half2 kh2 = *(__half2*)&kraw.z, kh3 = *(__half2*)&kraw.w;
        float2 k0 = __half22float2(kh0), k1 = __half22float2(kh1);
        float2 k2 = __half22float2(kh2), k3 = __half22float2(kh3);
        float dot = q[0]*k0.x + q[1]*k0.y + q[2]*k1.x + q[3]*k1.y
                  + q[4]*k2.x + q[5]*k2.y + q[6]*k3.x + q[7]*k3.y;
        dot += __shfl_xor_sync(0xFFFFFFFFu, dot, 1);
        dot += __shfl_xor_sync(0xFFFFFFFFu, dot, 2);

        float mnew = fmaxf(m, dot);
        float corr = __expf(m - mnew);
        float w    = __expf(dot - mnew);
        l = l * corr + w;

        uint4 vraw = *(const uint4*)(Kp + 256);
        __half2 vh0 = *(__half2*)&vraw.x, vh1 = *(__half2*)&vraw.y;
        __half2 vh2 = *(__half2*)&vraw.z, vh3 = *(__half2*)&vraw.w;
        float2 v0 = __half22float2(vh0), v1 = __half22float2(vh1);
        float2 v2 = __half22float2(vh2), v3 = __half22float2(vh3);
        acc[0] = acc[0] * corr + w * v0.x;
        acc[1] = acc[1] * corr + w * v0.y;
        acc[2] = acc[2] * corr + w * v1.x;
        acc[3] = acc[3] * corr + w * v1.y;
        acc[4] = acc[4] * corr + w * v2.x;
        acc[5] = acc[5] * corr + w * v2.y;
        acc[6] = acc[6] * corr + w * v3.x;
        acc[7] = acc[7] * corr + w * v3.y;
        m = mnew;
    }

    float inv = 1.f / l;
    float* outp = g_attn + (size_t)gw * 256 + (lane << 3);
#pragma unroll
    for (int i = 0; i < 8; i++) outp[i] = acc[i] * inv;
}

// ---------------- launch ----------------
extern "C" void kernel_launch(void* const* d_in, const int* in_sizes, int n_in,
                              void* d_out, int out_size) {
    const float* x      = (const float*)d_in[0];
    const int*   ei     = (const int*)d_in[1];
    const int*   xi     = (const int*)d_in[2];
    const float* W_qkv  = (const float*)d_in[3];
    const float* b_qkv  = (const float*)d_in[4];
    const float* W_out  = (const float*)d_in[5];
    const float* b_out  = (const float*)d_in[6];
    const float* gtok   = (const float*)d_in[7];
    float* out = (float*)d_out;

    float*  qkv_ptr;  cudaGetSymbolAddress((void**)&qkv_ptr, g_qkv);
    float*  attn_ptr; cudaGetSymbolAddress((void**)&attn_ptr, g_attn);
    __half* kvh_ptr;  cudaGetSymbolAddress((void**)&kvh_ptr, g_kvh);

    // CSR build
    zero_counts_kernel<<<N_NODES / 256, 256>>>();
    count_kernel<<<(E_LOCAL + 255) / 256, 256>>>(ei, xi);
    scan_kernel<<<1, 512>>>();
    fill_kernel<<<(E_LOCAL + 255) / 256, 256>>>(ei, xi);

    // QKV projection: [16388, 256] x [256, 768] + b  (also emits fp16 K/V)
    {
        dim3 grid(768 / 128, (NTOTAL + 127) / 128);
        gemm_bias_tc_kernel<<<grid, 256>>>(x, gtok, N_NODES, NTOTAL, 768,
                                           W_qkv, b_qkv, qkv_ptr, kvh_ptr);
    }

    // attention: one warp per node
    attn_kernel<<<(N_NODES * 32) / 256, 256>>>();

    // out projection: [16384, 256] x [256, 256] + b
    {
        dim3 grid(256 / 128, N_NODES / 128);
        gemm_bias_tc_kernel<<<grid, 256>>>(attn_ptr, attn_ptr, N_NODES, N_NODES, 256,
                                           W_out, b_out, out, nullptr);
    }
}

// round 7
// speedup vs baseline: 1.7407x; 1.2120x over previous
#include <cuda_runtime.h>
#include <cuda_bf16.h>
#include <cuda_fp16.h>
#include <math.h>
#include <stdint.h>

#define N_NODES 16384
#define NGLOB   4
#define NTOTAL  (N_NODES + NGLOB)
#define DIM     256
#define HEADS   8
#define DHEAD   32
#define E_LOCAL 131072
#define E_EXP   65536
#define E_CSR   (E_LOCAL + E_EXP)

// ---------------- scratch (static device allocations only) ----------------
__device__ float  g_qkv[(size_t)NTOTAL * 3 * DIM];   // [row][q|k|v (256 each)] fp32
__device__ __half g_kvh[(size_t)NTOTAL * 2 * DIM];   // [row][k 256 | v 256] fp16
__device__ float  g_attn[(size_t)N_NODES * DIM];
__device__ int    g_count[N_NODES];
__device__ int    g_off[N_NODES + 1];
__device__ int    g_wptr[N_NODES];
__device__ int    g_srcbuf[E_CSR];
// pre-split bf16 operand buffers
__device__ __nv_bfloat16 g_Ahi[(size_t)NTOTAL * DIM];
__device__ __nv_bfloat16 g_Alo[(size_t)NTOTAL * DIM];
__device__ __nv_bfloat16 g_Whi[(size_t)DIM * 768];
__device__ __nv_bfloat16 g_Wlo[(size_t)DIM * 768];

// ---------------- helpers ----------------
__device__ __forceinline__ uint32_t smem_u32(const void* p) {
    return (uint32_t)__cvta_generic_to_shared(p);
}
__device__ __forceinline__ void cp_async16(uint32_t s, const void* g) {
    asm volatile("cp.async.cg.shared.global [%0], [%1], 16;" :: "r"(s), "l"(g));
}
__device__ __forceinline__ void ldsm_x4(uint32_t addr, uint32_t& r0, uint32_t& r1,
                                        uint32_t& r2, uint32_t& r3) {
    asm volatile("ldmatrix.sync.aligned.m8n8.x4.shared.b16 {%0,%1,%2,%3}, [%4];"
                 : "=r"(r0), "=r"(r1), "=r"(r2), "=r"(r3) : "r"(addr));
}
__device__ __forceinline__ void ldsm_x4_t(uint32_t addr, uint32_t& r0, uint32_t& r1,
                                          uint32_t& r2, uint32_t& r3) {
    asm volatile("ldmatrix.sync.aligned.m8n8.x4.trans.shared.b16 {%0,%1,%2,%3}, [%4];"
                 : "=r"(r0), "=r"(r1), "=r"(r2), "=r"(r3) : "r"(addr));
}
__device__ __forceinline__ void mma_bf16(float* d, const uint32_t* a, const uint32_t* b) {
    asm volatile(
        "mma.sync.aligned.m16n8k16.row.col.f32.bf16.bf16.f32 "
        "{%0,%1,%2,%3},{%4,%5,%6,%7},{%8,%9},{%0,%1,%2,%3};"
        : "+f"(d[0]), "+f"(d[1]), "+f"(d[2]), "+f"(d[3])
        : "r"(a[0]), "r"(a[1]), "r"(a[2]), "r"(a[3]), "r"(b[0]), "r"(b[1]));
}

// ---------------- CSR build ----------------
__global__ void zero_counts_kernel() {
    int t = blockIdx.x * blockDim.x + threadIdx.x;
    if (t < N_NODES) g_count[t] = 0;
}

__global__ void count_kernel(const int* __restrict__ ei, const int* __restrict__ xi) {
    int t = blockIdx.x * blockDim.x + threadIdx.x;
    if (t < E_LOCAL) atomicAdd(&g_count[ei[E_LOCAL + t]], 1);
    if (t < E_EXP)   atomicAdd(&g_count[xi[E_EXP + t]], 1);
}

__global__ __launch_bounds__(512) void scan_kernel() {
    const int tid  = threadIdx.x;
    const int lane = tid & 31;
    const int wid  = tid >> 5;
    const int base = tid * 32;

    int vals[32];
#pragma unroll
    for (int i = 0; i < 32; i += 4) {
        int4 t = *(const int4*)&g_count[base + i];
        vals[i] = t.x; vals[i+1] = t.y; vals[i+2] = t.z; vals[i+3] = t.w;
    }
    int sum = 0;
#pragma unroll
    for (int i = 0; i < 32; i++) { int v = vals[i]; vals[i] = sum; sum += v; }

    int inc = sum;
#pragma unroll
    for (int o = 1; o < 32; o <<= 1) {
        int n = __shfl_up_sync(0xFFFFFFFFu, inc, o);
        if (lane >= o) inc += n;
    }
    __shared__ int wsum[16];
    if (lane == 31) wsum[wid] = inc;
    __syncthreads();
    if (wid == 0) {
        int w = (lane < 16) ? wsum[lane] : 0;
#pragma unroll
        for (int o = 1; o < 16; o <<= 1) {
            int n = __shfl_up_sync(0xFFFFFFFFu, w, o);
            if (lane >= o) w += n;
        }
        if (lane < 16) wsum[lane] = w;
    }
    __syncthreads();

    int offset = (wid ? wsum[wid - 1] : 0) + inc - sum;
#pragma unroll
    for (int i = 0; i < 32; i++) {
        int o = offset + vals[i];
        g_off[base + i]  = o;
        g_wptr[base + i] = o;
    }
    if (tid == 511) g_off[N_NODES] = wsum[15];
}

__global__ void fill_kernel(const int* __restrict__ ei, const int* __restrict__ xi) {
    int t = blockIdx.x * blockDim.x + threadIdx.x;
    if (t < E_LOCAL) {
        int d = ei[E_LOCAL + t];
        int p = atomicAdd(&g_wptr[d], 1);
        g_srcbuf[p] = ei[t];
    }
    if (t < E_EXP) {
        int d = xi[E_EXP + t];
        int p = atomicAdd(&g_wptr[d], 1);
        g_srcbuf[p] = xi[t];
    }
}

// ---------------- split fp32 -> bf16 hi/lo ----------------
__global__ void split_kernel(const float* __restrict__ src,
                             __nv_bfloat16* __restrict__ hi,
                             __nv_bfloat16* __restrict__ lo, int n2) {
    int t = blockIdx.x * blockDim.x + threadIdx.x;
    if (t >= n2) return;
    float2 v = ((const float2*)src)[t];
    __nv_bfloat162 h;
    h.x = __float2bfloat16(v.x); h.y = __float2bfloat16(v.y);
    __nv_bfloat162 l;
    l.x = __float2bfloat16(v.x - __bfloat162float(h.x));
    l.y = __float2bfloat16(v.y - __bfloat162float(h.y));
    ((__nv_bfloat162*)hi)[t] = h;
    ((__nv_bfloat162*)lo)[t] = l;
}

// ---------------- split-bf16 tensor-core GEMM (cp.async pipelined) ----------------
// C[M,Ncols] = A[M,256] * W[256,Ncols] + bias ; A,W pre-split into bf16 hi/lo.
// BM=128, BN=128, BK=32, double-buffered, 8 warps, 32x64 warp tiles.
#define AS_STRIDE 40
#define BS_STRIDE 136
#define AS_OFF(buf, p) ((((buf)*2 + (p)) * 128) * AS_STRIDE)
#define BS_OFF(buf, p) (20480 + (((buf)*2 + (p)) * 32) * BS_STRIDE)
#define GEMM_SMEM_ELEMS (20480 + 4 * 32 * BS_STRIDE)
#define GEMM_SMEM_BYTES (GEMM_SMEM_ELEMS * 2)

__global__ __launch_bounds__(256) void gemm_tc_kernel(
    const __nv_bfloat16* __restrict__ Ahi, const __nv_bfloat16* __restrict__ Alo,
    const __nv_bfloat16* __restrict__ Whi, const __nv_bfloat16* __restrict__ Wlo,
    const float* __restrict__ bias, float* __restrict__ C, int M, int Ncols,
    __half* __restrict__ kvh)
{
    extern __shared__ __nv_bfloat16 sm[];
    const int tid    = threadIdx.x;
    const int lane   = tid & 31;
    const int warp   = tid >> 5;
    const int warp_m = warp & 3;
    const int warp_n = warp >> 2;
    const int row0   = blockIdx.y * 128;
    const int col0   = blockIdx.x * 128;

    float acc[2][8][4];
#pragma unroll
    for (int i = 0; i < 2; i++)
#pragma unroll
        for (int j = 0; j < 8; j++)
#pragma unroll
            for (int q = 0; q < 4; q++) acc[i][j][q] = 0.f;

    const int fa_row  = warp_m * 32 + (lane & 15);
    const int fa_koff = (lane >> 4) << 3;
    const int fb_krow = (((lane >> 3) & 1) << 3) + (lane & 7);
    const int fb_n    = warp_n * 64 + ((lane >> 4) << 3);

    auto load_stage = [&](int kt, int buf) {
        const int k0 = kt * 32;
#pragma unroll
        for (int i = 0; i < 2; i++) {
            int c  = tid * 2 + i;
            int r  = c >> 2;
            int kk = (c & 3) * 8;
            int gr = row0 + r; if (gr >= M) gr = M - 1;
            size_t gidx = (size_t)gr * DIM + k0 + kk;
            cp_async16(smem_u32(&sm[AS_OFF(buf,0) + r * AS_STRIDE + kk]), Ahi + gidx);
            cp_async16(smem_u32(&sm[AS_OFF(buf,1) + r * AS_STRIDE + kk]), Alo + gidx);
        }
#pragma unroll
        for (int i = 0; i < 2; i++) {
            int c  = tid * 2 + i;
            int k  = c >> 4;
            int nn = (c & 15) * 8;
            size_t gidx = (size_t)(k0 + k) * Ncols + col0 + nn;
            cp_async16(smem_u32(&sm[BS_OFF(buf,0) + k * BS_STRIDE + nn]), Whi + gidx);
            cp_async16(smem_u32(&sm[BS_OFF(buf,1) + k * BS_STRIDE + nn]), Wlo + gidx);
        }
        asm volatile("cp.async.commit_group;" ::: "memory");
    };

    load_stage(0, 0);

    for (int kt = 0; kt < 8; kt++) {
        const int buf = kt & 1;
        if (kt + 1 < 8) {
            load_stage(kt + 1, buf ^ 1);
            asm volatile("cp.async.wait_group 1;" ::: "memory");
        } else {
            asm volatile("cp.async.wait_group 0;" ::: "memory");
        }
        __syncthreads();

#pragma unroll
        for (int ks = 0; ks < 32; ks += 16) {
            uint32_t ah[2][4], al[2][4], bh[8][2], bl[8][2];
#pragma unroll
            for (int mt = 0; mt < 2; mt++) {
                ldsm_x4(smem_u32(&sm[AS_OFF(buf,0) + (fa_row + mt*16) * AS_STRIDE + ks + fa_koff]),
                        ah[mt][0], ah[mt][1], ah[mt][2], ah[mt][3]);
                ldsm_x4(smem_u32(&sm[AS_OFF(buf,1) + (fa_row + mt*16) * AS_STRIDE + ks + fa_koff]),
                        al[mt][0], al[mt][1], al[mt][2], al[mt][3]);
            }
#pragma unroll
            for (int np = 0; np < 4; np++) {
                ldsm_x4_t(smem_u32(&sm[BS_OFF(buf,0) + (ks + fb_krow) * BS_STRIDE + fb_n + np*16]),
                          bh[np*2][0], bh[np*2][1], bh[np*2+1][0], bh[np*2+1][1]);
                ldsm_x4_t(smem_u32(&sm[BS_OFF(buf,1) + (ks + fb_krow) * BS_STRIDE + fb_n + np*16]),
                          bl[np*2][0], bl[np*2][1], bl[np*2+1][0], bl[np*2+1][1]);
            }
#pragma unroll
            for (int mt = 0; mt < 2; mt++)
#pragma unroll
                for (int nt = 0; nt < 8; nt++) {
                    mma_bf16(acc[mt][nt], ah[mt], bh[nt]);
                    mma_bf16(acc[mt][nt], ah[mt], bl[nt]);
                    mma_bf16(acc[mt][nt], al[mt], bh[nt]);
                }
        }
        __syncthreads();
    }

    // epilogue (+ optional fp16 K/V mirror for cols >= 256)
#pragma unroll
    for (int mt = 0; mt < 2; mt++) {
        int r_base = row0 + warp_m * 32 + mt * 16 + (lane >> 2);
#pragma unroll
        for (int nt = 0; nt < 8; nt++) {
            int c = col0 + warp_n * 64 + nt * 8 + (lane & 3) * 2;
            float b0 = bias[c], b1 = bias[c + 1];
            if (r_base < M) {
                float2 v = make_float2(acc[mt][nt][0] + b0, acc[mt][nt][1] + b1);
                *(float2*)&C[(size_t)r_base * Ncols + c] = v;
                if (kvh && c >= 256)
                    *(__half2*)&kvh[(size_t)r_base * 512 + (c - 256)] = __float22half2_rn(v);
            }
            if (r_base + 8 < M) {
                float2 v = make_float2(acc[mt][nt][2] + b0, acc[mt][nt][3] + b1);
                *(float2*)&C[(size_t)(r_base + 8) * Ncols + c] = v;
                if (kvh && c >= 256)
                    *(__half2*)&kvh[(size_t)(r_base + 8) * 512 + (c - 256)] = __float22half2_rn(v);
            }
        }
    }
}

// ---------------- attention: one warp per destination node, fp16 K/V (R6, unchanged) ----------------
__global__ __launch_bounds__(256) void attn_kernel() {
    int gw = (blockIdx.x * blockDim.x + threadIdx.x) >> 5;
    if (gw >= N_NODES) return;
    const int lane = threadIdx.x & 31;           // lane = head*4 + quarter
    const float scale = 0.17677669529663687f;    // 32^-0.5

    const float* Qp = g_qkv + (size_t)gw * 768 + (lane << 3);
    float q[8];
    {
        float4 q0 = *(const float4*)Qp;
        float4 q1 = *(const float4*)(Qp + 4);
        q[0] = q0.x * scale; q[1] = q0.y * scale; q[2] = q0.z * scale; q[3] = q0.w * scale;
        q[4] = q1.x * scale; q[5] = q1.y * scale; q[6] = q1.z * scale; q[7] = q1.w * scale;
    }

    float m = -INFINITY, l = 0.f;
    float acc[8];
#pragma unroll
    for (int i = 0; i < 8; i++) acc[i] = 0.f;

    const int s0   = g_off[gw];
    const int nloc = g_off[gw + 1] - s0;
    const int ntot = nloc + 1 + NGLOB;

    for (int it = 0; it < ntot; it++) {
        int src;
        if (it < nloc)          src = g_srcbuf[s0 + it];
        else if (it == nloc)    src = gw;
        else                    src = N_NODES + (it - nloc - 1);

        const __half* Kp = g_kvh + (size_t)src * 512 + (lane << 3);
        uint4 kraw = *(const uint4*)Kp;
        __half2 kh0 = *(__half2*)&kraw.x, kh1 = *(__half2*)&kraw.y;
        __half2 kh2 = *(__half2*)&kraw.z, kh3 = *(__half2*)&kraw.w;
        float2 k0 = __half22float2(kh0), k1 = __half22float2(kh1);
        float2 k2 = __half22float2(kh2), k3 = __half22float2(kh3);
        float dot = q[0]*k0.x + q[1]*k0.y + q[2]*k1.x + q[3]*k1.y
                  + q[4]*k2.x + q[5]*k2.y + q[6]*k3.x + q[7]*k3.y;
        dot += __shfl_xor_sync(0xFFFFFFFFu, dot, 1);
        dot += __shfl_xor_sync(0xFFFFFFFFu, dot, 2);

        float mnew = fmaxf(m, dot);
        float corr = __expf(m - mnew);
        float w    = __expf(dot - mnew);
        l = l * corr + w;

        uint4 vraw = *(const uint4*)(Kp + 256);
        __half2 vh0 = *(__half2*)&vraw.x, vh1 = *(__half2*)&vraw.y;
        __half2 vh2 = *(__half2*)&vraw.z, vh3 = *(__half2*)&vraw.w;
        float2 v0 = __half22float2(vh0), v1 = __half22float2(vh1);
        float2 v2 = __half22float2(vh2), v3 = __half22float2(vh3);
        acc[0] = acc[0] * corr + w * v0.x;
        acc[1] = acc[1] * corr + w * v0.y;
        acc[2] = acc[2] * corr + w * v1.x;
        acc[3] = acc[3] * corr + w * v1.y;
        acc[4] = acc[4] * corr + w * v2.x;
        acc[5] = acc[5] * corr + w * v2.y;
        acc[6] = acc[6] * corr + w * v3.x;
        acc[7] = acc[7] * corr + w * v3.y;
        m = mnew;
    }

    float inv = 1.f / l;
    float* outp = g_attn + (size_t)gw * 256 + (lane << 3);
#pragma unroll
    for (int i = 0; i < 8; i++) outp[i] = acc[i] * inv;
}

// ---------------- launch ----------------
extern "C" void kernel_launch(void* const* d_in, const int* in_sizes, int n_in,
                              void* d_out, int out_size) {
    const float* x      = (const float*)d_in[0];
    const int*   ei     = (const int*)d_in[1];
    const int*   xi     = (const int*)d_in[2];
    const float* W_qkv  = (const float*)d_in[3];
    const float* b_qkv  = (const float*)d_in[4];
    const float* W_out  = (const float*)d_in[5];
    const float* b_out  = (const float*)d_in[6];
    const float* gtok   = (const float*)d_in[7];
    float* out = (float*)d_out;

    float*  qkv_ptr;  cudaGetSymbolAddress((void**)&qkv_ptr, g_qkv);
    float*  attn_ptr; cudaGetSymbolAddress((void**)&attn_ptr, g_attn);
    __half* kvh_ptr;  cudaGetSymbolAddress((void**)&kvh_ptr, g_kvh);
    __nv_bfloat16 *Ahi, *Alo, *Whi, *Wlo;
    cudaGetSymbolAddress((void**)&Ahi, g_Ahi);
    cudaGetSymbolAddress((void**)&Alo, g_Alo);
    cudaGetSymbolAddress((void**)&Whi, g_Whi);
    cudaGetSymbolAddress((void**)&Wlo, g_Wlo);

    cudaFuncSetAttribute(gemm_tc_kernel,
                         cudaFuncAttributeMaxDynamicSharedMemorySize, GEMM_SMEM_BYTES);

    // CSR build
    zero_counts_kernel<<<N_NODES / 256, 256>>>();
    count_kernel<<<(E_LOCAL + 255) / 256, 256>>>(ei, xi);
    scan_kernel<<<1, 512>>>();
    fill_kernel<<<(E_LOCAL + 255) / 256, 256>>>(ei, xi);

    // split x, gtok, W_qkv
    split_kernel<<<(N_NODES * DIM / 2 + 255) / 256, 256>>>(x, Ahi, Alo, N_NODES * DIM / 2);
    split_kernel<<<2, 256>>>(gtok, Ahi + (size_t)N_NODES * DIM, Alo + (size_t)N_NODES * DIM,
                             NGLOB * DIM / 2);
    split_kernel<<<(DIM * 768 / 2 + 255) / 256, 256>>>(W_qkv, Whi, Wlo, DIM * 768 / 2);

    // QKV projection: [16388, 256] x [256, 768] + b  (also emits fp16 K/V)
    {
        dim3 grid(768 / 128, (NTOTAL + 127) / 128);
        gemm_tc_kernel<<<grid, 256, GEMM_SMEM_BYTES>>>(Ahi, Alo, Whi, Wlo,
                                                       b_qkv, qkv_ptr, NTOTAL, 768, kvh_ptr);
    }

    // attention: one warp per node
    attn_kernel<<<(N_NODES * 32) / 256, 256>>>();

    // split attn result + W_out
    split_kernel<<<(N_NODES * DIM / 2 + 255) / 256, 256>>>(attn_ptr, Ahi, Alo, N_NODES * DIM / 2);
    split_kernel<<<(DIM * DIM / 2 + 255) / 256, 256>>>(W_out, Whi, Wlo, DIM * DIM / 2);

    // out projection: [16384, 256] x [256, 256] + b
    {
        dim3 grid(256 / 128, N_NODES / 128);
        gemm_tc_kernel<<<grid, 256, GEMM_SMEM_BYTES>>>(Ahi, Alo, Whi, Wlo,
                                                       b_out, out, N_NODES, 256, nullptr);
    }
}

// round 8
// speedup vs baseline: 1.8675x; 1.0728x over previous
#include <cuda_runtime.h>
#include <cuda_bf16.h>
#include <cuda_fp16.h>
#include <math.h>
#include <stdint.h>

#define N_NODES 16384
#define NGLOB   4
#define NTOTAL  (N_NODES + NGLOB)
#define DIM     256
#define HEADS   8
#define DHEAD   32
#define E_LOCAL 131072
#define E_EXP   65536
#define E_CSR   (E_LOCAL + E_EXP)

// ---------------- scratch (static device allocations only) ----------------
__device__ float  g_qkv[(size_t)NTOTAL * 3 * DIM];   // only Q cols (0..255) written fp32
__device__ __half g_kvh[(size_t)NTOTAL * 2 * DIM];   // [row][k 256 | v 256] fp16
__device__ int    g_count[N_NODES];
__device__ int    g_off[N_NODES + 1];
__device__ int    g_wptr[N_NODES];
__device__ int    g_srcbuf[E_CSR];
// pre-split bf16 operand buffers
__device__ __nv_bfloat16 g_Ahi[(size_t)NTOTAL * DIM];
__device__ __nv_bfloat16 g_Alo[(size_t)NTOTAL * DIM];
__device__ __nv_bfloat16 g_Whi[(size_t)DIM * 768];
__device__ __nv_bfloat16 g_Wlo[(size_t)DIM * 768];

// ---------------- helpers ----------------
__device__ __forceinline__ uint32_t smem_u32(const void* p) {
    return (uint32_t)__cvta_generic_to_shared(p);
}
__device__ __forceinline__ void cp_async16(uint32_t s, const void* g) {
    asm volatile("cp.async.cg.shared.global [%0], [%1], 16;" :: "r"(s), "l"(g));
}
__device__ __forceinline__ void ldsm_x4(uint32_t addr, uint32_t& r0, uint32_t& r1,
                                        uint32_t& r2, uint32_t& r3) {
    asm volatile("ldmatrix.sync.aligned.m8n8.x4.shared.b16 {%0,%1,%2,%3}, [%4];"
                 : "=r"(r0), "=r"(r1), "=r"(r2), "=r"(r3) : "r"(addr));
}
__device__ __forceinline__ void ldsm_x4_t(uint32_t addr, uint32_t& r0, uint32_t& r1,
                                          uint32_t& r2, uint32_t& r3) {
    asm volatile("ldmatrix.sync.aligned.m8n8.x4.trans.shared.b16 {%0,%1,%2,%3}, [%4];"
                 : "=r"(r0), "=r"(r1), "=r"(r2), "=r"(r3) : "r"(addr));
}
__device__ __forceinline__ void mma_bf16(float* d, const uint32_t* a, const uint32_t* b) {
    asm volatile(
        "mma.sync.aligned.m16n8k16.row.col.f32.bf16.bf16.f32 "
        "{%0,%1,%2,%3},{%4,%5,%6,%7},{%8,%9},{%0,%1,%2,%3};"
        : "+f"(d[0]), "+f"(d[1]), "+f"(d[2]), "+f"(d[3])
        : "r"(a[0]), "r"(a[1]), "r"(a[2]), "r"(a[3]), "r"(b[0]), "r"(b[1]));
}

// ---------------- CSR build ----------------
__global__ void zero_counts_kernel() {
    int t = blockIdx.x * blockDim.x + threadIdx.x;
    if (t < N_NODES) g_count[t] = 0;
}

__global__ void count_kernel(const int* __restrict__ ei, const int* __restrict__ xi) {
    int t = blockIdx.x * blockDim.x + threadIdx.x;
    if (t < E_LOCAL) atomicAdd(&g_count[ei[E_LOCAL + t]], 1);
    if (t < E_EXP)   atomicAdd(&g_count[xi[E_EXP + t]], 1);
}

__global__ __launch_bounds__(512) void scan_kernel() {
    const int tid  = threadIdx.x;
    const int lane = tid & 31;
    const int wid  = tid >> 5;
    const int base = tid * 32;

    int vals[32];
#pragma unroll
    for (int i = 0; i < 32; i += 4) {
        int4 t = *(const int4*)&g_count[base + i];
        vals[i] = t.x; vals[i+1] = t.y; vals[i+2] = t.z; vals[i+3] = t.w;
    }
    int sum = 0;
#pragma unroll
    for (int i = 0; i < 32; i++) { int v = vals[i]; vals[i] = sum; sum += v; }

    int inc = sum;
#pragma unroll
    for (int o = 1; o < 32; o <<= 1) {
        int n = __shfl_up_sync(0xFFFFFFFFu, inc, o);
        if (lane >= o) inc += n;
    }
    __shared__ int wsum[16];
    if (lane == 31) wsum[wid] = inc;
    __syncthreads();
    if (wid == 0) {
        int w = (lane < 16) ? wsum[lane] : 0;
#pragma unroll
        for (int o = 1; o < 16; o <<= 1) {
            int n = __shfl_up_sync(0xFFFFFFFFu, w, o);
            if (lane >= o) w += n;
        }
        if (lane < 16) wsum[lane] = w;
    }
    __syncthreads();

    int offset = (wid ? wsum[wid - 1] : 0) + inc - sum;
#pragma unroll
    for (int i = 0; i < 32; i++) {
        int o = offset + vals[i];
        g_off[base + i]  = o;
        g_wptr[base + i] = o;
    }
    if (tid == 511) g_off[N_NODES] = wsum[15];
}

__global__ void fill_kernel(const int* __restrict__ ei, const int* __restrict__ xi) {
    int t = blockIdx.x * blockDim.x + threadIdx.x;
    if (t < E_LOCAL) {
        int d = ei[E_LOCAL + t];
        int p = atomicAdd(&g_wptr[d], 1);
        g_srcbuf[p] = ei[t];
    }
    if (t < E_EXP) {
        int d = xi[E_EXP + t];
        int p = atomicAdd(&g_wptr[d], 1);
        g_srcbuf[p] = xi[t];
    }
}

// ---------------- split fp32 -> bf16 hi/lo ----------------
__global__ void split_kernel(const float* __restrict__ src,
                             __nv_bfloat16* __restrict__ hi,
                             __nv_bfloat16* __restrict__ lo, int n2) {
    int t = blockIdx.x * blockDim.x + threadIdx.x;
    if (t >= n2) return;
    float2 v = ((const float2*)src)[t];
    __nv_bfloat162 h;
    h.x = __float2bfloat16(v.x); h.y = __float2bfloat16(v.y);
    __nv_bfloat162 l;
    l.x = __float2bfloat16(v.x - __bfloat162float(h.x));
    l.y = __float2bfloat16(v.y - __bfloat162float(h.y));
    ((__nv_bfloat162*)hi)[t] = h;
    ((__nv_bfloat162*)lo)[t] = l;
}

// ---------------- split-bf16 tensor-core GEMM (cp.async pipelined) ----------------
#define AS_STRIDE 40
#define BS_STRIDE 136
#define AS_OFF(buf, p) ((((buf)*2 + (p)) * 128) * AS_STRIDE)
#define BS_OFF(buf, p) (20480 + (((buf)*2 + (p)) * 32) * BS_STRIDE)
#define GEMM_SMEM_ELEMS (20480 + 4 * 32 * BS_STRIDE)
#define GEMM_SMEM_BYTES (GEMM_SMEM_ELEMS * 2)

// If kvh != nullptr ("QKV mode"): cols <256 -> fp32 C; cols >=256 -> fp16 kvh ONLY.
__global__ __launch_bounds__(256) void gemm_tc_kernel(
    const __nv_bfloat16* __restrict__ Ahi, const __nv_bfloat16* __restrict__ Alo,
    const __nv_bfloat16* __restrict__ Whi, const __nv_bfloat16* __restrict__ Wlo,
    const float* __restrict__ bias, float* __restrict__ C, int M, int Ncols,
    __half* __restrict__ kvh)
{
    extern __shared__ __nv_bfloat16 sm[];
    const int tid    = threadIdx.x;
    const int lane   = tid & 31;
    const int warp   = tid >> 5;
    const int warp_m = warp & 3;
    const int warp_n = warp >> 2;
    const int row0   = blockIdx.y * 128;
    const int col0   = blockIdx.x * 128;

    float acc[2][8][4];
#pragma unroll
    for (int i = 0; i < 2; i++)
#pragma unroll
        for (int j = 0; j < 8; j++)
#pragma unroll
            for (int q = 0; q < 4; q++) acc[i][j][q] = 0.f;

    const int fa_row  = warp_m * 32 + (lane & 15);
    const int fa_koff = (lane >> 4) << 3;
    const int fb_krow = (((lane >> 3) & 1) << 3) + (lane & 7);
    const int fb_n    = warp_n * 64 + ((lane >> 4) << 3);

    auto load_stage = [&](int kt, int buf) {
        const int k0 = kt * 32;
#pragma unroll
        for (int i = 0; i < 2; i++) {
            int c  = tid * 2 + i;
            int r  = c >> 2;
            int kk = (c & 3) * 8;
            int gr = row0 + r; if (gr >= M) gr = M - 1;
            size_t gidx = (size_t)gr * DIM + k0 + kk;
            cp_async16(smem_u32(&sm[AS_OFF(buf,0) + r * AS_STRIDE + kk]), Ahi + gidx);
            cp_async16(smem_u32(&sm[AS_OFF(buf,1) + r * AS_STRIDE + kk]), Alo + gidx);
        }
#pragma unroll
        for (int i = 0; i < 2; i++) {
            int c  = tid * 2 + i;
            int k  = c >> 4;
            int nn = (c & 15) * 8;
            size_t gidx = (size_t)(k0 + k) * Ncols + col0 + nn;
            cp_async16(smem_u32(&sm[BS_OFF(buf,0) + k * BS_STRIDE + nn]), Whi + gidx);
            cp_async16(smem_u32(&sm[BS_OFF(buf,1) + k * BS_STRIDE + nn]), Wlo + gidx);
        }
        asm volatile("cp.async.commit_group;" ::: "memory");
    };

    load_stage(0, 0);

    for (int kt = 0; kt < 8; kt++) {
        const int buf = kt & 1;
        if (kt + 1 < 8) {
            load_stage(kt + 1, buf ^ 1);
            asm volatile("cp.async.wait_group 1;" ::: "memory");
        } else {
            asm volatile("cp.async.wait_group 0;" ::: "memory");
        }
        __syncthreads();

#pragma unroll
        for (int ks = 0; ks < 32; ks += 16) {
            uint32_t ah[2][4], al[2][4], bh[8][2], bl[8][2];
#pragma unroll
            for (int mt = 0; mt < 2; mt++) {
                ldsm_x4(smem_u32(&sm[AS_OFF(buf,0) + (fa_row + mt*16) * AS_STRIDE + ks + fa_koff]),
                        ah[mt][0], ah[mt][1], ah[mt][2], ah[mt][3]);
                ldsm_x4(smem_u32(&sm[AS_OFF(buf,1) + (fa_row + mt*16) * AS_STRIDE + ks + fa_koff]),
                        al[mt][0], al[mt][1], al[mt][2], al[mt][3]);
            }
#pragma unroll
            for (int np = 0; np < 4; np++) {
                ldsm_x4_t(smem_u32(&sm[BS_OFF(buf,0) + (ks + fb_krow) * BS_STRIDE + fb_n + np*16]),
                          bh[np*2][0], bh[np*2][1], bh[np*2+1][0], bh[np*2+1][1]);
                ldsm_x4_t(smem_u32(&sm[BS_OFF(buf,1) + (ks + fb_krow) * BS_STRIDE + fb_n + np*16]),
                          bl[np*2][0], bl[np*2][1], bl[np*2+1][0], bl[np*2+1][1]);
            }
#pragma unroll
            for (int mt = 0; mt < 2; mt++)
#pragma unroll
                for (int nt = 0; nt < 8; nt++) {
                    mma_bf16(acc[mt][nt], ah[mt], bh[nt]);
                    mma_bf16(acc[mt][nt], ah[mt], bl[nt]);
                    mma_bf16(acc[mt][nt], al[mt], bh[nt]);
                }
        }
        __syncthreads();
    }

    // epilogue: QKV mode writes fp32 only for Q cols, fp16 only for K/V cols
#pragma unroll
    for (int mt = 0; mt < 2; mt++) {
        int r_base = row0 + warp_m * 32 + mt * 16 + (lane >> 2);
#pragma unroll
        for (int nt = 0; nt < 8; nt++) {
            int c = col0 + warp_n * 64 + nt * 8 + (lane & 3) * 2;
            float b0 = bias[c], b1 = bias[c + 1];
            const bool kv = (kvh != nullptr) && (c >= 256);
            if (r_base < M) {
                float2 v = make_float2(acc[mt][nt][0] + b0, acc[mt][nt][1] + b1);
                if (kv) *(__half2*)&kvh[(size_t)r_base * 512 + (c - 256)] = __float22half2_rn(v);
                else    *(float2*)&C[(size_t)r_base * Ncols + c] = v;
            }
            if (r_base + 8 < M) {
                float2 v = make_float2(acc[mt][nt][2] + b0, acc[mt][nt][3] + b1);
                if (kv) *(__half2*)&kvh[(size_t)(r_base + 8) * 512 + (c - 256)] = __float22half2_rn(v);
                else    *(float2*)&C[(size_t)(r_base + 8) * Ncols + c] = v;
            }
        }
    }
}

// ---------------- attention: one warp per dst node; emits bf16 hi/lo directly ----------------
__global__ __launch_bounds__(256) void attn_kernel() {
    int gw = (blockIdx.x * blockDim.x + threadIdx.x) >> 5;
    if (gw >= N_NODES) return;
    const int lane = threadIdx.x & 31;           // lane = head*4 + quarter
    const float scale = 0.17677669529663687f;    // 32^-0.5

    const float* Qp = g_qkv + (size_t)gw * 768 + (lane << 3);
    float q[8];
    {
        float4 q0 = *(const float4*)Qp;
        float4 q1 = *(const float4*)(Qp + 4);
        q[0] = q0.x * scale; q[1] = q0.y * scale; q[2] = q0.z * scale; q[3] = q0.w * scale;
        q[4] = q1.x * scale; q[5] = q1.y * scale; q[6] = q1.z * scale; q[7] = q1.w * scale;
    }

    float m = -INFINITY, l = 0.f;
    float acc[8];
#pragma unroll
    for (int i = 0; i < 8; i++) acc[i] = 0.f;

    const int s0   = g_off[gw];
    const int nloc = g_off[gw + 1] - s0;
    const int ntot = nloc + 1 + NGLOB;

    for (int it = 0; it < ntot; it++) {
        int src;
        if (it < nloc)          src = g_srcbuf[s0 + it];
        else if (it == nloc)    src = gw;
        else                    src = N_NODES + (it - nloc - 1);

        const __half* Kp = g_kvh + (size_t)src * 512 + (lane << 3);
        uint4 kraw = *(const uint4*)Kp;
        __half2 kh0 = *(__half2*)&kraw.x, kh1 = *(__half2*)&kraw.y;
        __half2 kh2 = *(__half2*)&kraw.z, kh3 = *(__half2*)&kraw.w;
        float2 k0 = __half22float2(kh0), k1 = __half22float2(kh1);
        float2 k2 = __half22float2(kh2), k3 = __half22float2(kh3);
        float dot = q[0]*k0.x + q[1]*k0.y + q[2]*k1.x + q[3]*k1.y
                  + q[4]*k2.x + q[5]*k2.y + q[6]*k3.x + q[7]*k3.y;
        dot += __shfl_xor_sync(0xFFFFFFFFu, dot, 1);
        dot += __shfl_xor_sync(0xFFFFFFFFu, dot, 2);

        float mnew = fmaxf(m, dot);
        float corr = __expf(m - mnew);
        float w    = __expf(dot - mnew);
        l = l * corr + w;

        uint4 vraw = *(const uint4*)(Kp + 256);
        __half2 vh0 = *(__half2*)&vraw.x, vh1 = *(__half2*)&vraw.y;
        __half2 vh2 = *(__half2*)&vraw.z, vh3 = *(__half2*)&vraw.w;
        float2 v0 = __half22float2(vh0), v1 = __half22float2(vh1);
        float2 v2 = __half22float2(vh2), v3 = __half22float2(vh3);
        acc[0] = acc[0] * corr + w * v0.x;
        acc[1] = acc[1] * corr + w * v0.y;
        acc[2] = acc[2] * corr + w * v1.x;
        acc[3] = acc[3] * corr + w * v1.y;
        acc[4] = acc[4] * corr + w * v2.x;
        acc[5] = acc[5] * corr + w * v2.y;
        acc[6] = acc[6] * corr + w * v3.x;
        acc[7] = acc[7] * corr + w * v3.y;
        m = mnew;
    }

    // epilogue: write bf16 hi/lo split directly (same math as split_kernel)
    float inv = 1.f / l;
    union { __nv_bfloat16 b[8]; uint4 u; } H, L;
#pragma unroll
    for (int i = 0; i < 8; i++) {
        float o = acc[i] * inv;
        __nv_bfloat16 h = __float2bfloat16(o);
        H.b[i] = h;
        L.b[i] = __float2bfloat16(o - __bfloat162float(h));
    }
    size_t oidx = (size_t)gw * 256 + (lane << 3);
    *(uint4*)&g_Ahi[oidx] = H.u;
    *(uint4*)&g_Alo[oidx] = L.u;
}

// ---------------- launch ----------------
extern "C" void kernel_launch(void* const* d_in, const int* in_sizes, int n_in,
                              void* d_out, int out_size) {
    const float* x      = (const float*)d_in[0];
    const int*   ei     = (const int*)d_in[1];
    const int*   xi     = (const int*)d_in[2];
    const float* W_qkv  = (const float*)d_in[3];
    const float* b_qkv  = (const float*)d_in[4];
    const float* W_out  = (const float*)d_in[5];
    const float* b_out  = (const float*)d_in[6];
    const float* gtok   = (const float*)d_in[7];
    float* out = (float*)d_out;

    float*  qkv_ptr;  cudaGetSymbolAddress((void**)&qkv_ptr, g_qkv);
    __half* kvh_ptr;  cudaGetSymbolAddress((void**)&kvh_ptr, g_kvh);
    __nv_bfloat16 *Ahi, *Alo, *Whi, *Wlo;
    cudaGetSymbolAddress((void**)&Ahi, g_Ahi);
    cudaGetSymbolAddress((void**)&Alo, g_Alo);
    cudaGetSymbolAddress((void**)&Whi, g_Whi);
    cudaGetSymbolAddress((void**)&Wlo, g_Wlo);

    cudaFuncSetAttribute(gemm_tc_kernel,
                         cudaFuncAttributeMaxDynamicSharedMemorySize, GEMM_SMEM_BYTES);

    // CSR build
    zero_counts_kernel<<<N_NODES / 256, 256>>>();
    count_kernel<<<(E_LOCAL + 255) / 256, 256>>>(ei, xi);
    scan_kernel<<<1, 512>>>();
    fill_kernel<<<(E_LOCAL + 255) / 256, 256>>>(ei, xi);

    // split x, gtok, W_qkv
    split_kernel<<<(N_NODES * DIM / 2 + 255) / 256, 256>>>(x, Ahi, Alo, N_NODES * DIM / 2);
    split_kernel<<<2, 256>>>(gtok, Ahi + (size_t)N_NODES * DIM, Alo + (size_t)N_NODES * DIM,
                             NGLOB * DIM / 2);
    split_kernel<<<(DIM * 768 / 2 + 255) / 256, 256>>>(W_qkv, Whi, Wlo, DIM * 768 / 2);

    // QKV projection: Q -> fp32 g_qkv, K/V -> fp16 g_kvh only
    {
        dim3 grid(768 / 128, (NTOTAL + 127) / 128);
        gemm_tc_kernel<<<grid, 256, GEMM_SMEM_BYTES>>>(Ahi, Alo, Whi, Wlo,
                                                       b_qkv, qkv_ptr, NTOTAL, 768, kvh_ptr);
    }

    // attention: one warp per node, writes bf16 hi/lo operands for GEMM2 directly
    attn_kernel<<<(N_NODES * 32) / 256, 256>>>();

    // split W_out
    split_kernel<<<(DIM * DIM / 2 + 255) / 256, 256>>>(W_out, Whi, Wlo, DIM * DIM / 2);

    // out projection: [16384, 256] x [256, 256] + b
    {
        dim3 grid(256 / 128, N_NODES / 128);
        gemm_tc_kernel<<<grid, 256, GEMM_SMEM_BYTES>>>(Ahi, Alo, Whi, Wlo,
                                                       b_out, out, N_NODES, 256, nullptr);
    }
}